// round 11
// baseline (speedup 1.0000x reference)
#include <cuda_runtime.h>
#include <cuda_bf16.h>

#define D4 32               // float4 per full row (D=128)
#define QPC 8               // float4-quads per CTA (32 cols = 128B contiguous/row)
#define THREADS 512
#define RB (THREADS / QPC)  // 64 row-bases
#define NWARP (THREADS / 32)
#define CROWS 384           // rows cached in smem (48 KB)

__global__ __launch_bounds__(THREADS, 4)
void graphnorm_vc(const float* __restrict__ x,
                  const float* __restrict__ gamma,
                  const float* __restrict__ beta,
                  const int* __restrict__ batch,
                  float* __restrict__ out)
{
    extern __shared__ float4 tile[];              // [CROWS][QPC] = 48 KB
    __shared__ float4 psum[NWARP][QPC];
    __shared__ float4 psq [NWARP][QPC];
    __shared__ float4 smean[QPC], sinv[QPC];

    const int cb   = blockIdx.x;                  // column block 0..3 (fastest)
    const int g    = blockIdx.y;                  // graph
    const int quad = threadIdx.x & (QPC - 1);     // 0..7
    const int rb   = threadIdx.x >> 3;            // 0..63
    const int warp = threadIdx.x >> 5;
    const int lane = threadIdx.x & 31;

    const int start = batch[g];
    const int end   = batch[g + 1];
    const int cnt   = end - start;
    const float fcnt = (float)cnt;
    const int crows = (cnt < CROWS) ? cnt : CROWS;

    const float4* __restrict__ xv = (const float4*)x;
    float4* __restrict__ ov = (float4*)out;
    const long colq = (long)cb * QPC + quad;      // float4 col 0..31

    // ---- pass 1: read slice, stash oldest rows in smem, accumulate ----
    float4 s = make_float4(0.f, 0.f, 0.f, 0.f);
    float4 q = make_float4(0.f, 0.f, 0.f, 0.f);
    for (int r = rb; r < cnt; r += RB) {
        float4 v = xv[(long)(start + r) * D4 + colq];
        if (r < CROWS) tile[r * QPC + quad] = v;  // victim cache for aged lines
        s.x += v.x; s.y += v.y; s.z += v.z; s.w += v.w;
        q.x += v.x * v.x; q.y += v.y * v.y; q.z += v.z * v.z; q.w += v.w * v.w;
    }

    // ---- warp reduce: lanes {quad, quad+8, quad+16, quad+24} share a column ----
    #pragma unroll
    for (int off = 8; off <= 16; off <<= 1) {
        s.x += __shfl_xor_sync(0xffffffffu, s.x, off);
        s.y += __shfl_xor_sync(0xffffffffu, s.y, off);
        s.z += __shfl_xor_sync(0xffffffffu, s.z, off);
        s.w += __shfl_xor_sync(0xffffffffu, s.w, off);
        q.x += __shfl_xor_sync(0xffffffffu, q.x, off);
        q.y += __shfl_xor_sync(0xffffffffu, q.y, off);
        q.z += __shfl_xor_sync(0xffffffffu, q.z, off);
        q.w += __shfl_xor_sync(0xffffffffu, q.w, off);
    }
    if (lane < QPC) { psum[warp][quad] = s; psq[warp][quad] = q; }
    __syncthreads();

    // ---- final reduce across warps + stats (QPC threads) ----
    if (threadIdx.x < QPC) {
        float4 ts = make_float4(0.f, 0.f, 0.f, 0.f);
        float4 tq = make_float4(0.f, 0.f, 0.f, 0.f);
        #pragma unroll
        for (int w = 0; w < NWARP; w++) {
            float4 a = psum[w][threadIdx.x];
            float4 b = psq [w][threadIdx.x];
            ts.x += a.x; ts.y += a.y; ts.z += a.z; ts.w += a.w;
            tq.x += b.x; tq.y += b.y; tq.z += b.z; tq.w += b.w;
        }
        float4 m, iv;
        m.x = ts.x / fcnt; m.y = ts.y / fcnt; m.z = ts.z / fcnt; m.w = ts.w / fcnt;
        float denom = fcnt - 1.0f;
        iv.x = 1.0f / (sqrtf(fmaxf((tq.x - fcnt * m.x * m.x) / denom, 0.f)) + 1e-5f);
        iv.y = 1.0f / (sqrtf(fmaxf((tq.y - fcnt * m.y * m.y) / denom, 0.f)) + 1e-5f);
        iv.z = 1.0f / (sqrtf(fmaxf((tq.z - fcnt * m.z * m.z) / denom, 0.f)) + 1e-5f);
        iv.w = 1.0f / (sqrtf(fmaxf((tq.w - fcnt * m.w * m.w) / denom, 0.f)) + 1e-5f);
        smean[threadIdx.x] = m;
        sinv [threadIdx.x] = iv;
    }
    __syncthreads();

    const float4 g4 = ((const float4*)gamma)[colq];
    const float4 b4 = ((const float4*)beta)[colq];
    const float4 m  = smean[quad];
    const float4 iv = sinv [quad];

    // ---- pass 2a: non-cached rows, REVERSE order (youngest L2 lines first) ----
    for (int j = rb; j < cnt - crows; j += RB) {
        const int r = cnt - 1 - j;                // descending from cnt-1 to crows
        const long idx = (long)(start + r) * D4 + colq;
        float4 v = __ldcs(&xv[idx]);              // evict-first: dead after read
        float4 o;
        o.x = g4.x * (v.x - m.x) * iv.x + b4.x;
        o.y = g4.y * (v.y - m.y) * iv.y + b4.y;
        o.z = g4.z * (v.z - m.z) * iv.z + b4.z;
        o.w = g4.w * (v.w - m.w) * iv.w + b4.w;
        __stcs(&ov[idx], o);                      // streaming store
    }

    // ---- pass 2b: cached rows served from smem (no DRAM/L2 read at all) ----
    for (int r = rb; r < crows; r += RB) {
        float4 v = tile[r * QPC + quad];
        const long idx = (long)(start + r) * D4 + colq;
        float4 o;
        o.x = g4.x * (v.x - m.x) * iv.x + b4.x;
        o.y = g4.y * (v.y - m.y) * iv.y + b4.y;
        o.z = g4.z * (v.z - m.z) * iv.z + b4.z;
        o.w = g4.w * (v.w - m.w) * iv.w + b4.w;
        __stcs(&ov[idx], o);
    }
}

extern "C" void kernel_launch(void* const* d_in, const int* in_sizes, int n_in,
                              void* d_out, int out_size)
{
    const float* x     = (const float*)d_in[0];
    const float* gamma = (const float*)d_in[1];
    const float* beta  = (const float*)d_in[2];
    const int*   batch = (const int*)d_in[3];
    float* out = (float*)d_out;

    const int G = in_sizes[3] - 1;
    const size_t smem = (size_t)CROWS * QPC * sizeof(float4);   // 48 KB

    cudaFuncSetAttribute(graphnorm_vc,
                         cudaFuncAttributeMaxDynamicSharedMemorySize, (int)smem);

    dim3 grid(D4 / QPC, G);   // (column-block fastest, graph)
    graphnorm_vc<<<grid, THREADS, smem>>>(x, gamma, beta, batch, out);
}

// round 12
// speedup vs baseline: 1.0210x; 1.0210x over previous
#include <cuda_runtime.h>
#include <cuda_bf16.h>
#include <cstdint>

#define D4 32               // float4 per full row (D=128)
#define QPC 8               // float4-quads per CTA (32 cols = 128B contiguous/row)
#define THREADS 512
#define RB (THREADS / QPC)  // 64 row-bases
#define NWARP (THREADS / 32)
#define CROWS 384           // rows cached in smem via cp.async (48 KB)

__device__ __forceinline__ void cp_async16(uint32_t smem_addr, const void* gmem) {
    asm volatile("cp.async.cg.shared.global [%0], [%1], 16;\n"
                 :: "r"(smem_addr), "l"(gmem) : "memory");
}

__global__ __launch_bounds__(THREADS, 4)
void graphnorm_vc2(const float* __restrict__ x,
                   const float* __restrict__ gamma,
                   const float* __restrict__ beta,
                   const int* __restrict__ batch,
                   float* __restrict__ out)
{
    extern __shared__ float4 tile[];              // [CROWS][QPC] = 48 KB
    __shared__ float4 psum[NWARP][QPC];
    __shared__ float4 psq [NWARP][QPC];
    __shared__ float4 smean[QPC], sinv[QPC];

    const int cb   = blockIdx.x;                  // column block 0..3 (fastest)
    const int g    = blockIdx.y;                  // graph
    const int quad = threadIdx.x & (QPC - 1);     // 0..7
    const int rb   = threadIdx.x >> 3;            // 0..63
    const int warp = threadIdx.x >> 5;
    const int lane = threadIdx.x & 31;

    const int start = batch[g];
    const int end   = batch[g + 1];
    const int cnt   = end - start;
    const float fcnt = (float)cnt;
    const int crows = (cnt < CROWS) ? cnt : CROWS;

    const float4* __restrict__ xv = (const float4*)x;
    float4* __restrict__ ov = (float4*)out;
    const long colq = (long)cb * QPC + quad;      // float4 col 0..31

    // ---- stage oldest rows into smem via cp.async (no register roundtrip) ----
    uint32_t tbase = (uint32_t)__cvta_generic_to_shared(tile);
    for (int r = rb; r < crows; r += RB) {
        cp_async16(tbase + (uint32_t)(r * QPC + quad) * 16u,
                   &xv[(long)(start + r) * D4 + colq]);
    }
    asm volatile("cp.async.commit_group;\n" ::: "memory");

    // ---- accumulate uncached rows straight from gmem (lines stay in L2) ----
    float4 s = make_float4(0.f, 0.f, 0.f, 0.f);
    float4 q = make_float4(0.f, 0.f, 0.f, 0.f);
    for (int r = crows + rb; r < cnt; r += RB) {
        float4 v = xv[(long)(start + r) * D4 + colq];
        s.x += v.x; s.y += v.y; s.z += v.z; s.w += v.w;
        q.x += v.x * v.x; q.y += v.y * v.y; q.z += v.z * v.z; q.w += v.w * v.w;
    }

    // ---- accumulate cached rows from smem ----
    asm volatile("cp.async.wait_group 0;\n" ::: "memory");
    __syncthreads();
    for (int r = rb; r < crows; r += RB) {
        float4 v = tile[r * QPC + quad];
        s.x += v.x; s.y += v.y; s.z += v.z; s.w += v.w;
        q.x += v.x * v.x; q.y += v.y * v.y; q.z += v.z * v.z; q.w += v.w * v.w;
    }

    // ---- warp reduce: lanes {quad, quad+8, quad+16, quad+24} share a column ----
    #pragma unroll
    for (int off = 8; off <= 16; off <<= 1) {
        s.x += __shfl_xor_sync(0xffffffffu, s.x, off);
        s.y += __shfl_xor_sync(0xffffffffu, s.y, off);
        s.z += __shfl_xor_sync(0xffffffffu, s.z, off);
        s.w += __shfl_xor_sync(0xffffffffu, s.w, off);
        q.x += __shfl_xor_sync(0xffffffffu, q.x, off);
        q.y += __shfl_xor_sync(0xffffffffu, q.y, off);
        q.z += __shfl_xor_sync(0xffffffffu, q.z, off);
        q.w += __shfl_xor_sync(0xffffffffu, q.w, off);
    }
    if (lane < QPC) { psum[warp][quad] = s; psq[warp][quad] = q; }
    __syncthreads();

    // ---- final reduce across warps + stats (QPC threads) ----
    if (threadIdx.x < QPC) {
        float4 ts = make_float4(0.f, 0.f, 0.f, 0.f);
        float4 tq = make_float4(0.f, 0.f, 0.f, 0.f);
        #pragma unroll
        for (int w = 0; w < NWARP; w++) {
            float4 a = psum[w][threadIdx.x];
            float4 b = psq [w][threadIdx.x];
            ts.x += a.x; ts.y += a.y; ts.z += a.z; ts.w += a.w;
            tq.x += b.x; tq.y += b.y; tq.z += b.z; tq.w += b.w;
        }
        float4 m, iv;
        m.x = ts.x / fcnt; m.y = ts.y / fcnt; m.z = ts.z / fcnt; m.w = ts.w / fcnt;
        float denom = fcnt - 1.0f;
        iv.x = 1.0f / (sqrtf(fmaxf((tq.x - fcnt * m.x * m.x) / denom, 0.f)) + 1e-5f);
        iv.y = 1.0f / (sqrtf(fmaxf((tq.y - fcnt * m.y * m.y) / denom, 0.f)) + 1e-5f);
        iv.z = 1.0f / (sqrtf(fmaxf((tq.z - fcnt * m.z * m.z) / denom, 0.f)) + 1e-5f);
        iv.w = 1.0f / (sqrtf(fmaxf((tq.w - fcnt * m.w * m.w) / denom, 0.f)) + 1e-5f);
        smean[threadIdx.x] = m;
        sinv [threadIdx.x] = iv;
    }
    __syncthreads();

    const float4 g4 = ((const float4*)gamma)[colq];
    const float4 b4 = ((const float4*)beta)[colq];
    const float4 m  = smean[quad];
    const float4 iv = sinv [quad];

    // ---- pass 2a: uncached rows from L2 (young, resident), streaming ----
    for (int r = crows + rb; r < cnt; r += RB) {
        const long idx = (long)(start + r) * D4 + colq;
        float4 v = __ldcs(&xv[idx]);              // evict-first: dead after read
        float4 o;
        o.x = g4.x * (v.x - m.x) * iv.x + b4.x;
        o.y = g4.y * (v.y - m.y) * iv.y + b4.y;
        o.z = g4.z * (v.z - m.z) * iv.z + b4.z;
        o.w = g4.w * (v.w - m.w) * iv.w + b4.w;
        __stcs(&ov[idx], o);
    }

    // ---- pass 2b: cached rows from smem (zero DRAM reads) ----
    for (int r = rb; r < crows; r += RB) {
        float4 v = tile[r * QPC + quad];
        const long idx = (long)(start + r) * D4 + colq;
        float4 o;
        o.x = g4.x * (v.x - m.x) * iv.x + b4.x;
        o.y = g4.y * (v.y - m.y) * iv.y + b4.y;
        o.z = g4.z * (v.z - m.z) * iv.z + b4.z;
        o.w = g4.w * (v.w - m.w) * iv.w + b4.w;
        __stcs(&ov[idx], o);
    }
}

extern "C" void kernel_launch(void* const* d_in, const int* in_sizes, int n_in,
                              void* d_out, int out_size)
{
    const float* x     = (const float*)d_in[0];
    const float* gamma = (const float*)d_in[1];
    const float* beta  = (const float*)d_in[2];
    const int*   batch = (const int*)d_in[3];
    float* out = (float*)d_out;

    const int G = in_sizes[3] - 1;
    const size_t smem = (size_t)CROWS * QPC * sizeof(float4);   // 48 KB

    cudaFuncSetAttribute(graphnorm_vc2,
                         cudaFuncAttributeMaxDynamicSharedMemorySize, (int)smem);

    dim3 grid(D4 / QPC, G);   // (column-block fastest, graph)
    graphnorm_vc2<<<grid, THREADS, smem>>>(x, gamma, beta, batch, out);
}